// round 5
// baseline (speedup 1.0000x reference)
#include <cuda_runtime.h>
#include <cuda_fp16.h>
#include <cstdint>
#include <cstddef>

#define NROW   200000
#define CIN    64
#define COUT   64
#define KOFF   27
#define KT     7                    // tensor group: k in [0,KT)
#define KS     (KOFF - KT)          // SIMT group: 20 offsets
#define TILE_M 128
#define NTILES ((NROW + TILE_M - 1) / TILE_M)   // 1563

// ---------------- device scratch ----------------
__device__ __align__(128) __half g_feats16[(NROW + 8) * CIN];   // row NROW = zeros
__device__ __align__(128) __half g_w16[KOFF * CIN * COUT];      // fp16 [k][cin][cout]
__device__ __align__(128) float  g_wf32[KOFF * CIN * COUT];     // fp32 [k][cin][cout]
__device__ int    g_idx2[KOFF * NROW];
__device__ float  g_conv[(size_t)NROW * COUT];
__device__ float  g_partials[NTILES * 128];
__device__ float  g_bn[128];

// ---------------- helpers ----------------
__device__ __forceinline__ uint32_t smem_u32(const void* p) {
    uint32_t a;
    asm("{ .reg .u64 t; cvta.to.shared.u64 t, %1; cvt.u32.u64 %0, t; }" : "=r"(a) : "l"(p));
    return a;
}
__device__ __forceinline__ void cp_async16(uint32_t dst, const void* src) {
    asm volatile("cp.async.cg.shared.global [%0], [%1], 16;" :: "r"(dst), "l"(src));
}
__device__ __forceinline__ void cp_commit() {
    asm volatile("cp.async.commit_group;" ::: "memory");
}
__device__ __forceinline__ void ldmatrix_x4(uint32_t* r, uint32_t addr) {
    asm volatile("ldmatrix.sync.aligned.m8n8.x4.shared.b16 {%0,%1,%2,%3}, [%4];"
                 : "=r"(r[0]), "=r"(r[1]), "=r"(r[2]), "=r"(r[3]) : "r"(addr));
}
__device__ __forceinline__ void ldmatrix_x4_t(uint32_t* r, uint32_t addr) {
    asm volatile("ldmatrix.sync.aligned.m8n8.x4.trans.shared.b16 {%0,%1,%2,%3}, [%4];"
                 : "=r"(r[0]), "=r"(r[1]), "=r"(r[2]), "=r"(r[3]) : "r"(addr));
}
__device__ __forceinline__ void mma16816(float* d, const uint32_t* a, uint32_t b0, uint32_t b1) {
    asm volatile(
        "mma.sync.aligned.m16n8k16.row.col.f32.f16.f16.f32 "
        "{%0,%1,%2,%3}, {%4,%5,%6,%7}, {%8,%9}, {%0,%1,%2,%3};"
        : "+f"(d[0]), "+f"(d[1]), "+f"(d[2]), "+f"(d[3])
        : "r"(a[0]), "r"(a[1]), "r"(a[2]), "r"(a[3]), "r"(b0), "r"(b1));
}
#define BAR_T() asm volatile("bar.sync 1, 128;" ::: "memory")
#define BAR_S() asm volatile("bar.sync 2, 128;" ::: "memory")

// ---------------- SMEM layout ----------------
#define A_STRIDE 144
#define A_STAGE  (128 * A_STRIDE)    // 18432
#define B_STRIDE 144
#define B_STAGE  (64 * B_STRIDE)     // 9216
#define SW_STRIDE 272                // 64 f32 + 16B pad
#define OFF_TA   0                   // tensor A x2 : [0, 36864)
#define OFF_TB   36864               // tensor B x2 : [36864, 55296)
#define OFF_SA   55296               // SIMT A x2  : [55296, 92160)
#define OFF_SW   92160               // SIMT W x1  : [92160, 109568)
#define SMEM_BYTES 109568
#define OFF_STATS1 0                 // tensor results [64][129] f32 (33024 B)
#define OFF_STATS2 55296             // SIMT results   [64][129] f32
#define OFF_PS   36864               // partial sums (in TB area)

// ---------------- prep kernels ----------------
__global__ void prep_feats_kernel(const float* __restrict__ feats) {
    int i = blockIdx.x * 256 + threadIdx.x;
    if (i < NROW * (CIN / 4)) {
        float4 v = reinterpret_cast<const float4*>(feats)[i];
        __half2* dst = reinterpret_cast<__half2*>(g_feats16);
        dst[i * 2]     = __floats2half2_rn(v.x, v.y);
        dst[i * 2 + 1] = __floats2half2_rn(v.z, v.w);
    } else if (i < NROW * (CIN / 4) + (CIN / 4)) {
        __half2 z = __float2half2_rn(0.0f);
        __half2* dst = reinterpret_cast<__half2*>(g_feats16);
        dst[i * 2]     = z;
        dst[i * 2 + 1] = z;
    }
}
__global__ void prep_w_kernel(const float* __restrict__ W) {
    int i = blockIdx.x * 256 + threadIdx.x;
    if (i < KOFF * CIN * COUT) {
        float w = W[i];
        g_w16[i]  = __float2half_rn(w);
        g_wf32[i] = w;
    }
}
__global__ void prep_idx_kernel(const int* __restrict__ nbr, const int* __restrict__ mask) {
    int i = blockIdx.x * 256 + threadIdx.x;
    if (i < KOFF * NROW) g_idx2[i] = mask[i] ? nbr[i] : NROW;
}

// ---------------- tensor-group loader (threads 0..127) ----------------
__device__ __forceinline__ void t_load_stage(uint32_t sb, int tid, int m0, int k) {
    int s = k & 1;
    uint32_t abuf = sb + OFF_TA + s * A_STAGE;
    uint32_t bbuf = sb + OFF_TB + s * B_STAGE;
    const int* idxk = g_idx2 + k * NROW;
    int ch = tid & 7;
    #pragma unroll
    for (int it = 0; it < 8; it++) {
        int r = it * 16 + (tid >> 3);
        int m = m0 + r;
        int src = (m < NROW) ? __ldg(idxk + m) : NROW;
        cp_async16(abuf + (uint32_t)(r * A_STRIDE + ch * 16),
                   (const char*)g_feats16 + ((size_t)src * (CIN * 2) + ch * 16));
    }
    const char* wsrc = (const char*)g_w16 + (size_t)k * (CIN * COUT * 2);
    #pragma unroll
    for (int it = 0; it < 4; it++) {
        int r = it * 16 + (tid >> 3);
        cp_async16(bbuf + (uint32_t)(r * B_STRIDE + ch * 16), wsrc + r * 128 + ch * 16);
    }
    cp_commit();
}

// ---------------- SIMT-group loaders (t4 = tid-128) ----------------
__device__ __forceinline__ void s_load_A(uint32_t sb, int t4, int m0, int k, int buf) {
    uint32_t abuf = sb + OFF_SA + buf * A_STAGE;
    const int* idxk = g_idx2 + k * NROW;
    int ch = t4 & 7;
    #pragma unroll
    for (int it = 0; it < 8; it++) {
        int r = it * 16 + (t4 >> 3);
        int m = m0 + r;
        int src = (m < NROW) ? __ldg(idxk + m) : NROW;
        cp_async16(abuf + (uint32_t)(r * A_STRIDE + ch * 16),
                   (const char*)g_feats16 + ((size_t)src * (CIN * 2) + ch * 16));
    }
}
__device__ __forceinline__ void s_load_W(uint32_t sb, int t4, int k) {
    const char* wsrc = (const char*)g_wf32 + (size_t)k * (CIN * COUT * 4);
    #pragma unroll
    for (int it = 0; it < 8; it++) {
        int id = it * 128 + t4;
        int row = id >> 4, c16 = id & 15;
        cp_async16(sb + OFF_SW + (uint32_t)(row * SW_STRIDE + c16 * 16),
                   wsrc + row * 256 + c16 * 16);
    }
}

// ---------------- SIMT compute: one k-offset via fma.rn.f32x2 ----------------
__device__ __forceinline__ void s_compute(uint32_t sb, int buf, int thr_r, int c0,
                                          unsigned long long acc[8][4]) {
    uint32_t abase = sb + OFF_SA + buf * A_STAGE + (uint32_t)(thr_r * A_STRIDE);
    uint32_t wbase = sb + OFF_SW + (uint32_t)(c0 * 4);
    #pragma unroll 4
    for (int c4 = 0; c4 < 16; c4++) {         // cin in chunks of 4
        uint32_t ha[8][2];
        #pragma unroll
        for (int i = 0; i < 8; i++) {          // rows thr_r + 16*i
            asm volatile("ld.shared.v2.b32 {%0,%1}, [%2];"
                : "=r"(ha[i][0]), "=r"(ha[i][1])
                : "r"(abase + (uint32_t)(i * 16 * A_STRIDE + c4 * 8)));
        }
        #pragma unroll
        for (int c1 = 0; c1 < 4; c1++) {
            unsigned long long w0, w1, w2, w3;
            uint32_t waddr = wbase + (uint32_t)((c4 * 4 + c1) * SW_STRIDE);
            asm volatile("ld.shared.v2.u64 {%0,%1}, [%2];" : "=l"(w0), "=l"(w1) : "r"(waddr));
            asm volatile("ld.shared.v2.u64 {%0,%1}, [%2];" : "=l"(w2), "=l"(w3) : "r"(waddr + 16));
            #pragma unroll
            for (int i = 0; i < 8; i++) {
                uint32_t hw = ha[i][c1 >> 1];
                __half2 h2 = *reinterpret_cast<__half2*>(&hw);
                float a = (c1 & 1) ? __high2float(h2) : __low2float(h2);
                unsigned long long ad;
                asm("mov.b64 %0, {%1, %1};" : "=l"(ad) : "r"(__float_as_uint(a)));
                asm("fma.rn.f32x2 %0, %1, %2, %0;" : "+l"(acc[i][0]) : "l"(ad), "l"(w0));
                asm("fma.rn.f32x2 %0, %1, %2, %0;" : "+l"(acc[i][1]) : "l"(ad), "l"(w1));
                asm("fma.rn.f32x2 %0, %1, %2, %0;" : "+l"(acc[i][2]) : "l"(ad), "l"(w2));
                asm("fma.rn.f32x2 %0, %1, %2, %0;" : "+l"(acc[i][3]) : "l"(ad), "l"(w3));
            }
        }
    }
}

// ---------------- main hybrid kernel ----------------
__global__ void __launch_bounds__(256, 2) conv_mma_kernel() {
    extern __shared__ char smem[];
    uint32_t sb = smem_u32(smem);
    int tid = threadIdx.x;
    int m0 = blockIdx.x * TILE_M;
    float* stats1 = (float*)(smem + OFF_STATS1);
    float* stats2 = (float*)(smem + OFF_STATS2);

    if (tid < 128) {
        // ============ TENSOR GROUP: k in [0, KT) ============
        int lane = tid & 31, wid = tid >> 5;
        float d[2][8][4];
        #pragma unroll
        for (int i = 0; i < 2; i++)
            #pragma unroll
            for (int j = 0; j < 8; j++)
                #pragma unroll
                for (int l = 0; l < 4; l++) d[i][j][l] = 0.f;

        t_load_stage(sb, tid, m0, 0);
        uint32_t a_off = (uint32_t)((wid * 32 + (lane & 15)) * A_STRIDE + (lane >> 4) * 16);
        uint32_t b_off = (uint32_t)((lane & 15) * B_STRIDE + (lane >> 4) * 16);

        #pragma unroll 1
        for (int k = 0; k < KT; k++) {
            if (k < KT - 1) {
                t_load_stage(sb, tid, m0, k + 1);
                asm volatile("cp.async.wait_group 1;" ::: "memory");
            } else {
                asm volatile("cp.async.wait_group 0;" ::: "memory");
            }
            BAR_T();
            uint32_t abase = sb + OFF_TA + (k & 1) * A_STAGE + a_off;
            uint32_t bbase = sb + OFF_TB + (k & 1) * B_STAGE + b_off;
            #pragma unroll
            for (int kk = 0; kk < 4; kk++) {
                uint32_t a0 = abase + kk * 32;
                uint32_t bk = bbase + kk * 16 * B_STRIDE;
                uint32_t afr[2][4], bfr[4][4];
                ldmatrix_x4(afr[0], a0);
                ldmatrix_x4(afr[1], a0 + 16 * A_STRIDE);
                #pragma unroll
                for (int jb = 0; jb < 4; jb++) ldmatrix_x4_t(bfr[jb], bk + jb * 32);
                #pragma unroll
                for (int mi = 0; mi < 2; mi++)
                    #pragma unroll
                    for (int nn = 0; nn < 8; nn++)
                        mma16816(d[mi][nn], afr[mi],
                                 bfr[nn >> 1][(nn & 1) * 2], bfr[nn >> 1][(nn & 1) * 2 + 1]);
            }
            BAR_T();
        }
        {   // write tensor results into stats1 (TA area; all tensor reads done)
            int r0 = wid * 32 + (lane >> 2);
            int c0 = (lane & 3) * 2;
            #pragma unroll
            for (int mi = 0; mi < 2; mi++)
                #pragma unroll
                for (int nn = 0; nn < 8; nn++) {
                    int r = r0 + mi * 16;
                    int c = c0 + nn * 8;
                    stats1[(c + 0) * 129 + r]     = d[mi][nn][0];
                    stats1[(c + 1) * 129 + r]     = d[mi][nn][1];
                    stats1[(c + 0) * 129 + r + 8] = d[mi][nn][2];
                    stats1[(c + 1) * 129 + r + 8] = d[mi][nn][3];
                }
        }
    } else {
        // ============ SIMT GROUP: k in [KT, 27) ============
        int t4 = tid - 128;
        int thr_r = t4 & 15;          // row within 16-row groups
        int c0 = (t4 >> 4) * 8;       // 8 couts per thread
        unsigned long long acc[8][4];
        #pragma unroll
        for (int i = 0; i < 8; i++)
            #pragma unroll
            for (int j = 0; j < 4; j++) acc[i][j] = 0ull;

        s_load_A(sb, t4, m0, KT, 0);     cp_commit();   // [A0]
        s_load_W(sb, t4, KT);            cp_commit();   // [W0]
        s_load_A(sb, t4, m0, KT + 1, 1); cp_commit();   // [A1]

        #pragma unroll 1
        for (int j = 0; j < KS; j++) {
            if (j == KS - 1) asm volatile("cp.async.wait_group 0;" ::: "memory");
            else             asm volatile("cp.async.wait_group 1;" ::: "memory");
            BAR_S();
            s_compute(sb, j & 1, thr_r, c0, acc);
            BAR_S();
            if (j < KS - 1) { s_load_W(sb, t4, KT + j + 1); cp_commit(); }          // [W_{j+1}]
            if (j < KS - 2) { s_load_A(sb, t4, m0, KT + j + 2, j & 1); cp_commit(); } // [A_{j+2}]
        }
        // write SIMT results into stats2 (SA area; all SIMT reads done)
        #pragma unroll
        for (int i = 0; i < 8; i++) {
            int r = thr_r + 16 * i;
            #pragma unroll
            for (int jj = 0; jj < 4; jj++) {
                uint32_t lo, hi;
                asm("mov.b64 {%0, %1}, %2;" : "=r"(lo), "=r"(hi) : "l"(acc[i][jj]));
                stats2[(c0 + 2 * jj + 0) * 129 + r] = __uint_as_float(lo);
                stats2[(c0 + 2 * jj + 1) * 129 + r] = __uint_as_float(hi);
            }
        }
    }
    __syncthreads();

    // ---------------- common epilogue (256 threads) ----------------
    #pragma unroll
    for (int it = 0; it < 8; it++) {
        int idx = it * 256 + tid;
        int r = idx >> 4, c4 = idx & 15;
        int m = m0 + r;
        if (m < NROW) {
            float4 v;
            v.x = stats1[(c4 * 4 + 0) * 129 + r] + stats2[(c4 * 4 + 0) * 129 + r];
            v.y = stats1[(c4 * 4 + 1) * 129 + r] + stats2[(c4 * 4 + 1) * 129 + r];
            v.z = stats1[(c4 * 4 + 2) * 129 + r] + stats2[(c4 * 4 + 2) * 129 + r];
            v.w = stats1[(c4 * 4 + 3) * 129 + r] + stats2[(c4 * 4 + 3) * 129 + r];
            reinterpret_cast<float4*>(g_conv + (size_t)m * COUT)[c4] = v;
        }
    }
    {   // per-tile channel sums, fixed order -> deterministic
        int c = tid & 63, part = tid >> 6;
        float s = 0.f, s2 = 0.f;
        #pragma unroll
        for (int i = 0; i < 32; i++) {
            int r = part * 32 + i;
            float v = stats1[c * 129 + r] + stats2[c * 129 + r];
            s += v; s2 += v * v;
        }
        float* ps = (float*)(smem + OFF_PS);
        ps[part * 64 + c]       = s;
        ps[256 + part * 64 + c] = s2;
    }
    __syncthreads();
    if (tid < 64) {
        const float* ps = (const float*)(smem + OFF_PS);
        float S  = ps[tid] + ps[64 + tid] + ps[128 + tid] + ps[192 + tid];
        float S2 = ps[256 + tid] + ps[320 + tid] + ps[384 + tid] + ps[448 + tid];
        g_partials[blockIdx.x * 128 + tid]      = S;
        g_partials[blockIdx.x * 128 + 64 + tid] = S2;
    }
}

// ---------------- BN stats finalize ----------------
__global__ void bn_stats_kernel(const float* __restrict__ gamma, const float* __restrict__ beta) {
    __shared__ float sh[256];
    int tid = threadIdx.x;
    int c = tid & 127, seg = tid >> 7;
    const int half = (NTILES + 1) / 2;
    int lo = seg * half;
    int hi = lo + half; if (hi > NTILES) hi = NTILES;
    float s = 0.f;
    #pragma unroll 4
    for (int t = lo; t < hi; t++) s += g_partials[t * 128 + c];
    sh[tid] = s;
    __syncthreads();
    if (tid < 64) {
        float S  = sh[tid]      + sh[128 + tid];
        float S2 = sh[64 + tid] + sh[192 + tid];
        const float invN = 1.0f / (float)NROW;
        float mean = S * invN;
        float var  = S2 * invN - mean * mean;
        float inv  = rsqrtf(var + 1e-5f);
        float sc   = inv * gamma[tid];
        g_bn[tid]      = sc;
        g_bn[64 + tid] = beta[tid] - mean * sc;
    }
}

// ---------------- BN apply + ReLU ----------------
__global__ void bn_apply_kernel(float* __restrict__ out) {
    int i = blockIdx.x * 256 + threadIdx.x;
    if (i >= NROW * (COUT / 4)) return;
    int c = (i & 15) << 2;
    float4 v = reinterpret_cast<const float4*>(g_conv)[i];
    float4 r;
    r.x = fmaxf(fmaf(v.x, __ldg(&g_bn[c + 0]), __ldg(&g_bn[64 + c + 0])), 0.f);
    r.y = fmaxf(fmaf(v.y, __ldg(&g_bn[c + 1]), __ldg(&g_bn[64 + c + 1])), 0.f);
    r.z = fmaxf(fmaf(v.z, __ldg(&g_bn[c + 2]), __ldg(&g_bn[64 + c + 2])), 0.f);
    r.w = fmaxf(fmaf(v.w, __ldg(&g_bn[c + 3]), __ldg(&g_bn[64 + c + 3])), 0.f);
    reinterpret_cast<float4*>(out)[i] = r;
}

// ---------------- launch ----------------
extern "C" void kernel_launch(void* const* d_in, const int* in_sizes, int n_in,
                              void* d_out, int out_size) {
    const float* feats = (const float*)d_in[0];
    const float* W     = (const float*)d_in[1];
    const float* gamma = (const float*)d_in[2];
    const float* beta  = (const float*)d_in[3];
    const int*   nbr   = (const int*)d_in[4];
    const int*   mask  = (const int*)d_in[5];
    float* out = (float*)d_out;

    cudaFuncSetAttribute(conv_mma_kernel, cudaFuncAttributeMaxDynamicSharedMemorySize, SMEM_BYTES);

    prep_feats_kernel<<<(NROW * (CIN / 4) + (CIN / 4) + 255) / 256, 256>>>(feats);
    prep_w_kernel<<<(KOFF * CIN * COUT + 255) / 256, 256>>>(W);
    prep_idx_kernel<<<(KOFF * NROW + 255) / 256, 256>>>(nbr, mask);
    conv_mma_kernel<<<NTILES, 256, SMEM_BYTES>>>();
    bn_stats_kernel<<<1, 256>>>(gamma, beta);
    bn_apply_kernel<<<(NROW * (COUT / 4) + 255) / 256, 256>>>(out);
}